// round 1
// baseline (speedup 1.0000x reference)
#include <cuda_runtime.h>

typedef unsigned long long u64;
typedef unsigned int u32;

#define MAXN 250048

// Scratch (allocation-free rule: __device__ globals)
__device__ float g_X  [(size_t)MAXN * 64];
__device__ float g_F1 [(size_t)MAXN * 64];
__device__ float g_D0 [(size_t)MAXN * 32];
__device__ float g_D1 [(size_t)MAXN * 32];
__device__ float g_A8 [(size_t)MAXN * 8];
__device__ float g_T8 [(size_t)MAXN * 8];
__device__ float g_T8B[(size_t)MAXN * 8];

__device__ __forceinline__ u64 pack2(float x) {
    u64 r;
    asm("mov.b64 %0, {%1, %1};" : "=l"(r) : "r"(__float_as_uint(x)));
    return r;
}

__device__ __forceinline__ void fma2(u64& acc, u64 a, u64 b) {
    asm("fma.rn.f32x2 %0, %1, %2, %0;" : "+l"(acc) : "l"(a), "l"(b));
}

__device__ __forceinline__ float2 unpack2(u64 v) {
    float2 r;
    r.x = __uint_as_float((u32)(v & 0xffffffffull));
    r.y = __uint_as_float((u32)(v >> 32));
    return r;
}

// ---------------------------------------------------------------------------
// Sparse conv: out[p, :] = sum_k  X[idx[p,k], :] @ W[k]  (+bias, +resid, relu)
// Register-tiled gather-GEMM, f32x2 packed accumulators over channel pairs.
// Thread layout: cg = tid % CGROUPS (channel group of CTT), pg = tid / CGROUPS
// (point group of PTT).  TP = PGROUPS*PTT points per CTA.
// ---------------------------------------------------------------------------
template<int K, int CIN, int COUT, int PGROUPS, int CGROUPS, int PTT, int CTT,
         bool RELU, bool RESID, int OSTRIDE, int OCOFF, bool WALL>
__global__ void __launch_bounds__(PGROUPS * CGROUPS)
spconv_kernel(const float* __restrict__ X, const int* __restrict__ idx,
              const float* __restrict__ W, const float* __restrict__ B,
              const float* __restrict__ R, float* __restrict__ out, int Nout)
{
    constexpr int TP   = PGROUPS * PTT;
    constexpr int NTHR = PGROUPS * CGROUPS;
    constexpr int GS   = CIN + 1;          // pad to avoid bank conflicts

    extern __shared__ float smem[];
    float* gbuf = smem;                    // TP * GS
    float* Wsh  = smem + TP * GS;          // WALL ? K*CIN*COUT : CIN*COUT

    const int tid = threadIdx.x;
    const int cg  = tid % CGROUPS;
    const int pg  = tid / CGROUPS;
    const int p0  = blockIdx.x * TP;

    if (WALL) {
        constexpr int WTOT = K * CIN * COUT / 4;
        const float4* Wg = (const float4*)W;
        float4* Ws4 = (float4*)Wsh;
        for (int e = tid; e < WTOT; e += NTHR) Ws4[e] = Wg[e];
    }

    u64 acc[PTT][CTT / 2];
#pragma unroll
    for (int a = 0; a < PTT; a++)
#pragma unroll
        for (int b = 0; b < CTT / 2; b++) acc[a][b] = 0ull;

    for (int k = 0; k < K; k++) {
        __syncthreads();   // protect gbuf (and Wsh when streaming) reuse
        if (!WALL) {
            constexpr int WTOT = CIN * COUT / 4;
            const float4* Wg = (const float4*)W;
            float4* Ws4 = (float4*)Wsh;
            for (int e = tid; e < WTOT; e += NTHR)
                Ws4[e] = Wg[(size_t)k * WTOT + e];
        }
        // gather tile for this kernel offset
        constexpr int C4 = CIN / 4;
        for (int e = tid; e < TP * C4; e += NTHR) {
            int p  = e / C4;
            int c4 = e % C4;
            int gp = p0 + p;
            float4 v = make_float4(0.f, 0.f, 0.f, 0.f);
            if (gp < Nout) {
                int src = idx[(size_t)gp * K + k];
                if (src >= 0) v = ((const float4*)(X + (size_t)src * CIN))[c4];
            }
            float* d = gbuf + p * GS + 4 * c4;
            d[0] = v.x; d[1] = v.y; d[2] = v.z; d[3] = v.w;
        }
        __syncthreads();

        const float* Wk = WALL ? (Wsh + k * CIN * COUT) : Wsh;
        const float* gb = gbuf + pg * PTT * GS;
        const float* wb = Wk + cg * CTT;
#pragma unroll 4
        for (int ci = 0; ci < CIN; ci++) {
            u64 wv[CTT / 2];
            if constexpr (CTT == 8) {
                ulonglong2 t0 = *(const ulonglong2*)(wb + ci * COUT);
                ulonglong2 t1 = *(const ulonglong2*)(wb + ci * COUT + 4);
                wv[0] = t0.x; wv[1] = t0.y; wv[2] = t1.x; wv[3] = t1.y;
            } else if constexpr (CTT == 4) {
                ulonglong2 t0 = *(const ulonglong2*)(wb + ci * COUT);
                wv[0] = t0.x; wv[1] = t0.y;
            } else {
                wv[0] = *(const u64*)(wb + ci * COUT);
            }
#pragma unroll
            for (int pp = 0; pp < PTT; pp++) {
                u64 g2 = pack2(gb[pp * GS + ci]);
#pragma unroll
                for (int cc = 0; cc < CTT / 2; cc++)
                    fma2(acc[pp][cc], g2, wv[cc]);
            }
        }
    }

    // epilogue: bias (+resid) (+relu), channel-pair stores
#pragma unroll
    for (int pp = 0; pp < PTT; pp++) {
        int p = p0 + pg * PTT + pp;
        if (p < Nout) {
#pragma unroll
            for (int cc = 0; cc < CTT / 2; cc++) {
                int c = cg * CTT + 2 * cc;
                float2 v = unpack2(acc[pp][cc]);
                v.x += B[c];
                v.y += B[c + 1];
                if (RESID) {
                    float2 rv = *(const float2*)(R + (size_t)p * OSTRIDE + OCOFF + c);
                    v.x += rv.x; v.y += rv.y;
                }
                if (RELU) { v.x = fmaxf(v.x, 0.f); v.y = fmaxf(v.y, 0.f); }
                *(float2*)(out + (size_t)p * OSTRIDE + OCOFF + c) = v;
            }
        }
    }
}

// ---------------------------------------------------------------------------
// Pointwise (kernel-size-1) conv: out[p,:] = X[p,:] @ W (+bias, +resid, relu)
// ---------------------------------------------------------------------------
template<int CIN, int COUT, bool RELU, bool RESID, int OSTRIDE, int OCOFF>
__global__ void pw_kernel(const float* __restrict__ X, const float* __restrict__ W,
                          const float* __restrict__ B, const float* __restrict__ R,
                          float* __restrict__ out, int Nout)
{
    __shared__ float Wsh[CIN * COUT];
    for (int e = threadIdx.x; e < CIN * COUT; e += blockDim.x) Wsh[e] = W[e];
    __syncthreads();

    int p = blockIdx.x * blockDim.x + threadIdx.x;
    if (p >= Nout) return;

    float acc[COUT];
#pragma unroll
    for (int c = 0; c < COUT; c++) acc[c] = B[c];

    const float4* xr = (const float4*)(X + (size_t)p * CIN);
#pragma unroll
    for (int c4 = 0; c4 < CIN / 4; c4++) {
        float4 v = xr[c4];
        const float* w0 = Wsh + (4 * c4) * COUT;
#pragma unroll
        for (int c = 0; c < COUT; c++) {
            acc[c] += v.x * w0[c] + v.y * w0[COUT + c]
                    + v.z * w0[2 * COUT + c] + v.w * w0[3 * COUT + c];
        }
    }
#pragma unroll
    for (int c = 0; c < COUT; c++) {
        float v = acc[c];
        if (RESID) v += R[(size_t)p * OSTRIDE + OCOFF + c];
        if (RELU)  v = fmaxf(v, 0.f);
        out[(size_t)p * OSTRIDE + OCOFF + c] = v;
    }
}

__global__ void add_kernel(const float* __restrict__ a, const float* __restrict__ b,
                           float* __restrict__ o, long long n4)
{
    long long i = blockIdx.x * (long long)blockDim.x + threadIdx.x;
    if (i < n4) {
        float4 x = ((const float4*)a)[i];
        float4 y = ((const float4*)b)[i];
        x.x += y.x; x.y += y.y; x.z += y.z; x.w += y.w;
        ((float4*)o)[i] = x;
    }
}

// ---------------------------------------------------------------------------
template<int K, int CIN, int COUT, int PG, int CG, int PTT, int CTT,
         bool RELU, bool RESID, int OS, int OC, bool WALL>
static void launch_conv(const float* X, const int* idx, const float* W,
                        const float* B, const float* R, float* out, int Nout)
{
    constexpr int TP   = PG * PTT;
    constexpr int NTHR = PG * CG;
    constexpr int SMEM = (TP * (CIN + 1) + (WALL ? K * CIN * COUT : CIN * COUT)) * 4;
    auto kfn = spconv_kernel<K, CIN, COUT, PG, CG, PTT, CTT, RELU, RESID, OS, OC, WALL>;
    cudaFuncSetAttribute(kfn, cudaFuncAttributeMaxDynamicSharedMemorySize, SMEM);
    int grid = (Nout + TP - 1) / TP;
    kfn<<<grid, NTHR, SMEM>>>(X, idx, W, B, R, out, Nout);
}

extern "C" void kernel_launch(void* const* d_in, const int* in_sizes, int n_in,
                              void* d_out, int out_size)
{
    const float* x_feat = (const float*)d_in[0];
    const float* f1_ref = (const float*)d_in[1];
    const float* w1   = (const float*)d_in[2];
    const float* b1   = (const float*)d_in[3];
    const float* wd   = (const float*)d_in[4];
    const float* bd   = (const float*)d_in[5];
    const float* rw00 = (const float*)d_in[6];
    const float* rb00 = (const float*)d_in[7];
    const float* rw01 = (const float*)d_in[8];
    const float* rb01 = (const float*)d_in[9];
    const float* rw10 = (const float*)d_in[10];
    const float* rb10 = (const float*)d_in[11];
    const float* rw11 = (const float*)d_in[12];
    const float* rb11 = (const float*)d_in[13];
    const float* rw12 = (const float*)d_in[14];
    const float* rb12 = (const float*)d_in[15];
    const float* w4   = (const float*)d_in[16];
    const float* b4   = (const float*)d_in[17];
    const int* idx1 = (const int*)d_in[18];
    const int* idxd = (const int*)d_in[19];
    const int* idx2 = (const int*)d_in[20];

    int N  = in_sizes[0] / 64;
    int N2 = in_sizes[19] / 8;

    float *X, *F1, *D0, *D1, *A8, *T8, *T8B;
    cudaGetSymbolAddress((void**)&X,   g_X);
    cudaGetSymbolAddress((void**)&F1,  g_F1);
    cudaGetSymbolAddress((void**)&D0,  g_D0);
    cudaGetSymbolAddress((void**)&D1,  g_D1);
    cudaGetSymbolAddress((void**)&A8,  g_A8);
    cudaGetSymbolAddress((void**)&T8,  g_T8);
    cudaGetSymbolAddress((void**)&T8B, g_T8B);

    // x = x_feat + f1_ref
    long long n4 = (long long)N * 16;
    add_kernel<<<(int)((n4 + 255) / 256), 256>>>(x_feat, f1_ref, X, n4);

    // conv1: K=27, 64->64, relu  (W streamed per-k: 442KB total)
    launch_conv<27, 64, 64, 16, 8, 8, 8, true, false, 64, 0, false>(
        X, idx1, w1, b1, nullptr, F1, N);

    // down: K=8, 64->32, relu (whole W resident: 64KB)
    launch_conv<8, 64, 32, 16, 8, 8, 4, true, false, 32, 0, true>(
        F1, idxd, wd, bd, nullptr, D0, N2);

    float* bufs[2] = { D0, D1 };
    for (int i = 0; i < 3; i++) {
        float* in = bufs[i & 1];
        float* ob = bufs[(i + 1) & 1];

        // a8 = relu(conv27(in, rw00))          32 -> 8
        launch_conv<27, 32, 8, 32, 4, 8, 2, true, false, 8, 0, true>(
            in, idx2, rw00 + (size_t)i * 27 * 32 * 8, rb00 + i * 8, nullptr, A8, N2);

        // out0 = conv27(a8, rw01) + in[:, :16]  -> ob[:, :16]   8 -> 16
        launch_conv<27, 8, 16, 32, 4, 8, 4, false, true, 32, 0, true>(
            A8, idx2, rw01 + (size_t)i * 27 * 8 * 16, rb01 + i * 16, in, ob, N2);

        // t = relu(in @ rw10)                  32 -> 8
        pw_kernel<32, 8, true, false, 8, 0><<<(N2 + 255) / 256, 256>>>(
            in, rw10 + i * 32 * 8, rb10 + i * 8, nullptr, T8, N2);

        // t = relu(conv27(t, rw11))            8 -> 8
        launch_conv<27, 8, 8, 32, 4, 8, 2, true, false, 8, 0, true>(
            T8, idx2, rw11 + (size_t)i * 27 * 8 * 8, rb11 + i * 8, nullptr, T8B, N2);

        // out1 = t @ rw12 + in[:, 16:]  -> ob[:, 16:]   8 -> 16
        pw_kernel<8, 16, false, true, 32, 16><<<(N2 + 255) / 256, 256>>>(
            T8B, rw12 + i * 8 * 16, rb12 + i * 16, in, ob, N2);
    }

    // enc4: K=27, 32 -> 8, no relu, straight to output
    launch_conv<27, 32, 8, 32, 4, 8, 2, false, false, 8, 0, true>(
        bufs[1], idx2, w4, b4, nullptr, (float*)d_out, N2);
}

// round 2
// speedup vs baseline: 2.0245x; 2.0245x over previous
#include <cuda_runtime.h>

typedef unsigned long long u64;
typedef unsigned int u32;

#define MAXN 250048

// Scratch (allocation-free rule: __device__ globals)
__device__ float g_X  [(size_t)MAXN * 64];
__device__ float g_F1 [(size_t)MAXN * 64];
__device__ float g_D0 [(size_t)MAXN * 32];
__device__ float g_D1 [(size_t)MAXN * 32];
__device__ float g_A8 [(size_t)MAXN * 8];
__device__ float g_T8 [(size_t)MAXN * 8];
__device__ float g_T8B[(size_t)MAXN * 8];
__device__ int   g_iT1[(size_t)MAXN * 27];
__device__ int   g_iT2[(size_t)MAXN * 27];
__device__ int   g_iTd[(size_t)MAXN * 8];

__device__ __forceinline__ u64 pack2(float x) {
    u64 r;
    asm("mov.b64 %0, {%1, %1};" : "=l"(r) : "r"(__float_as_uint(x)));
    return r;
}
__device__ __forceinline__ void fma2(u64& acc, u64 a, u64 b) {
    asm("fma.rn.f32x2 %0, %1, %2, %0;" : "+l"(acc) : "l"(a), "l"(b));
}
__device__ __forceinline__ float2 unpack2(u64 v) {
    float2 r;
    r.x = __uint_as_float((u32)(v & 0xffffffffull));
    r.y = __uint_as_float((u32)(v >> 32));
    return r;
}
__device__ __forceinline__ u32 smem_u32(const void* p) {
    return (u32)__cvta_generic_to_shared(p);
}
__device__ __forceinline__ void cpasync16(u32 dst, const void* src, u32 ssz) {
    asm volatile("cp.async.ca.shared.global [%0], [%1], 16, %2;\n"
                 :: "r"(dst), "l"(src), "r"(ssz));
}
__device__ __forceinline__ void cp_commit() {
    asm volatile("cp.async.commit_group;\n");
}
template<int N>
__device__ __forceinline__ void cp_wait() {
    asm volatile("cp.async.wait_group %0;\n" :: "n"(N));
}

// ---------------------------------------------------------------------------
// idx transpose: outT[k*Npt + p] = in[p*K + k]
// ---------------------------------------------------------------------------
__global__ void transpose_idx(const int* __restrict__ in, int* __restrict__ outT,
                              int Npt, int K)
{
    int p = blockIdx.x * blockDim.x + threadIdx.x;
    if (p < Npt)
        for (int k = 0; k < K; k++)
            outT[(size_t)k * Npt + p] = in[(size_t)p * K + k];
}

// ---------------------------------------------------------------------------
// Tiled gather-GEMM sparse conv with cp.async double-buffered pipeline.
// CTT fixed at 8 (4 f32x2 accumulators per point per thread).
// gbuf layout: 16B units, unit(p, c4) = p*C4U + (c4 ^ (p&7))  (conflict-free)
// Requires TP == NTHR (each thread gathers exactly one point per k).
// ---------------------------------------------------------------------------
template<int K, int CIN, int COUT, int NTHR, int CG, int PTT,
         bool RELU, bool RESID, int OS, int OC, bool WSTREAM>
__global__ void __launch_bounds__(NTHR)
spconv_tile(const float* __restrict__ X, const int* __restrict__ idxT,
            const float* __restrict__ W, const float* __restrict__ B,
            const float* __restrict__ R, float* __restrict__ out, int Nout)
{
    constexpr int PG  = NTHR / CG;
    constexpr int TP  = PG * PTT;
    static_assert(TP == NTHR, "gather assumes TP == NTHR");
    constexpr int C4U = CIN / 4;
    static_assert(C4U >= 8, "swizzle needs CIN >= 32");
    constexpr int CTT = 8;
    constexpr int WSZ = CIN * COUT;       // floats per kernel offset

    extern __shared__ float smem[];
    float* gbuf0 = smem;                  // TP*CIN
    float* gbuf1 = smem + TP * CIN;
    float* Wsh0  = smem + 2 * TP * CIN;
    float* Wsh1  = WSTREAM ? (Wsh0 + WSZ) : Wsh0;

    const int tid = threadIdx.x;
    const int cg  = tid % CG;
    const int pg  = tid / CG;
    const int p0  = blockIdx.x * TP;
    const int p   = tid;                  // gather point within tile
    const int gp  = p0 + p;
    const bool pv = gp < Nout;

    const u32 gb_u[2] = { smem_u32(gbuf0), smem_u32(gbuf1) };
    const u32 wb_u[2] = { smem_u32(Wsh0),  smem_u32(Wsh1)  };

    if (!WSTREAM) {
        // whole W resident: async-load once (joins group 0)
        const float4* Wg = (const float4*)W;
        for (int e = tid; e < K * WSZ / 4; e += NTHR)
            cpasync16(wb_u[0] + 16u * e, Wg + e, 16);
    }

    auto prefetch = [&](int k, int b) {
        int src = pv ? idxT[(size_t)k * Nout + gp] : -1;
        const float* srow = X + (size_t)(src >= 0 ? src : 0) * CIN;
        u32 ssz = (src >= 0) ? 16u : 0u;
        u32 base = gb_u[b] + (u32)p * (CIN * 4);
#pragma unroll
        for (int c4 = 0; c4 < C4U; c4++)
            cpasync16(base + ((u32)(c4 ^ (p & 7)) << 4), srow + 4 * c4, ssz);
        if (WSTREAM) {
            const float4* Wg = (const float4*)(W + (size_t)k * WSZ);
            for (int e = tid; e < WSZ / 4; e += NTHR)
                cpasync16(wb_u[b] + 16u * e, Wg + e, 16);
        }
    };

    prefetch(0, 0);
    cp_commit();

    u64 acc[PTT][4];
#pragma unroll
    for (int a = 0; a < PTT; a++)
#pragma unroll
        for (int c = 0; c < 4; c++) acc[a][c] = 0ull;

    constexpr int U = (C4U > 8) ? 4 : C4U;   // inner unroll of channel-quads

#pragma unroll 1
    for (int k = 0; k < K; k++) {
        __syncthreads();                     // prev compute done -> safe to refill
        if (k + 1 < K) { prefetch(k + 1, (k + 1) & 1); cp_commit(); cp_wait<1>(); }
        else           { cp_wait<0>(); }
        __syncthreads();                     // tile k visible to all

        const float* gb = (k & 1) ? gbuf1 : gbuf0;
        const float* Wk = WSTREAM ? ((k & 1) ? Wsh1 : Wsh0)
                                  : (Wsh0 + (size_t)k * WSZ);
        const float* wcol = Wk + cg * CTT;

#pragma unroll 1
        for (int c4o = 0; c4o < C4U; c4o += U) {
#pragma unroll
            for (int c4i = 0; c4i < U; c4i++) {
                const int c4 = c4o + c4i;
                u64 wv[4][4];
#pragma unroll
                for (int j = 0; j < 4; j++) {
                    const float* wr = wcol + (4 * c4 + j) * COUT;
                    ulonglong2 t0 = *(const ulonglong2*)wr;
                    ulonglong2 t1 = *(const ulonglong2*)(wr + 4);
                    wv[j][0] = t0.x; wv[j][1] = t0.y;
                    wv[j][2] = t1.x; wv[j][3] = t1.y;
                }
#pragma unroll
                for (int pp = 0; pp < PTT; pp++) {
                    const int pt = pg * PTT + pp;
                    const float4 g4 = *(const float4*)
                        (gb + (size_t)pt * CIN + ((c4 ^ (pt & 7)) << 2));
                    u64 g2;
                    g2 = pack2(g4.x);
                    fma2(acc[pp][0], g2, wv[0][0]); fma2(acc[pp][1], g2, wv[0][1]);
                    fma2(acc[pp][2], g2, wv[0][2]); fma2(acc[pp][3], g2, wv[0][3]);
                    g2 = pack2(g4.y);
                    fma2(acc[pp][0], g2, wv[1][0]); fma2(acc[pp][1], g2, wv[1][1]);
                    fma2(acc[pp][2], g2, wv[1][2]); fma2(acc[pp][3], g2, wv[1][3]);
                    g2 = pack2(g4.z);
                    fma2(acc[pp][0], g2, wv[2][0]); fma2(acc[pp][1], g2, wv[2][1]);
                    fma2(acc[pp][2], g2, wv[2][2]); fma2(acc[pp][3], g2, wv[2][3]);
                    g2 = pack2(g4.w);
                    fma2(acc[pp][0], g2, wv[3][0]); fma2(acc[pp][1], g2, wv[3][1]);
                    fma2(acc[pp][2], g2, wv[3][2]); fma2(acc[pp][3], g2, wv[3][3]);
                }
            }
        }
    }

    // epilogue
    const int c0 = cg * CTT;
#pragma unroll
    for (int pp = 0; pp < PTT; pp++) {
        int pt = p0 + pg * PTT + pp;
        if (pt < Nout) {
            float2 v0 = unpack2(acc[pp][0]);
            float2 v1 = unpack2(acc[pp][1]);
            float2 v2 = unpack2(acc[pp][2]);
            float2 v3 = unpack2(acc[pp][3]);
            float4 o0 = make_float4(v0.x + B[c0], v0.y + B[c0 + 1],
                                    v1.x + B[c0 + 2], v1.y + B[c0 + 3]);
            float4 o1 = make_float4(v2.x + B[c0 + 4], v2.y + B[c0 + 5],
                                    v3.x + B[c0 + 6], v3.y + B[c0 + 7]);
            float* op = out + (size_t)pt * OS + OC + c0;
            if (RESID) {
                const float* rp = R + (size_t)pt * OS + OC + c0;
                float4 r0 = *(const float4*)rp;
                float4 r1 = *(const float4*)(rp + 4);
                o0.x += r0.x; o0.y += r0.y; o0.z += r0.z; o0.w += r0.w;
                o1.x += r1.x; o1.y += r1.y; o1.z += r1.z; o1.w += r1.w;
            }
            if (RELU) {
                o0.x = fmaxf(o0.x, 0.f); o0.y = fmaxf(o0.y, 0.f);
                o0.z = fmaxf(o0.z, 0.f); o0.w = fmaxf(o0.w, 0.f);
                o1.x = fmaxf(o1.x, 0.f); o1.y = fmaxf(o1.y, 0.f);
                o1.z = fmaxf(o1.z, 0.f); o1.w = fmaxf(o1.w, 0.f);
            }
            *(float4*)op = o0;
            *(float4*)(op + 4) = o1;
        }
    }
}

// ---------------------------------------------------------------------------
// Direct sparse conv for CIN=8 (rows are 32B): thread per point, neighbor rows
// loaded straight from global (L2-resident), register double-buffered over k.
// ---------------------------------------------------------------------------
template<int K, int COUT, bool RELU, bool RESID, int OS, int OC>
__global__ void __launch_bounds__(256)
spconv_direct8(const float* __restrict__ X, const int* __restrict__ idxT,
               const float* __restrict__ W, const float* __restrict__ B,
               const float* __restrict__ R, float* __restrict__ out, int Nout)
{
    constexpr int NA = COUT / 2;
    __shared__ float Wsh[K * 8 * COUT];
    for (int e = threadIdx.x; e < K * 8 * COUT; e += 256) Wsh[e] = W[e];
    __syncthreads();

    const int p = blockIdx.x * 256 + threadIdx.x;
    if (p >= Nout) return;

    u64 acc[NA];
#pragma unroll
    for (int c = 0; c < NA; c++) acc[c] = 0ull;

    const float4 z4 = make_float4(0.f, 0.f, 0.f, 0.f);
    int s_nxt = (K > 1) ? idxT[(size_t)Nout + p] : -1;
    int s0 = idxT[p];
    float4 a0 = z4, a1 = z4;
    if (s0 >= 0) {
        const float4* r = (const float4*)(X + (size_t)s0 * 8);
        a0 = r[0]; a1 = r[1];
    }

#pragma unroll 1
    for (int k = 0; k < K; k++) {
        float4 b0 = z4, b1 = z4;
        if (k + 1 < K) {
            if (s_nxt >= 0) {
                const float4* r = (const float4*)(X + (size_t)s_nxt * 8);
                b0 = r[0]; b1 = r[1];
            }
            s_nxt = (k + 2 < K) ? idxT[(size_t)(k + 2) * Nout + p] : -1;
        }
        const float* wk = Wsh + k * 8 * COUT;
        const float g[8] = { a0.x, a0.y, a0.z, a0.w, a1.x, a1.y, a1.z, a1.w };
#pragma unroll
        for (int ci = 0; ci < 8; ci++) {
            u64 g2 = pack2(g[ci]);
            const u64* wr = (const u64*)(wk + ci * COUT);
#pragma unroll
            for (int cc = 0; cc < NA; cc++)
                fma2(acc[cc], g2, wr[cc]);
        }
        a0 = b0; a1 = b1;
    }

    float* op = out + (size_t)p * OS + OC;
#pragma unroll
    for (int q = 0; q < NA / 2; q++) {
        float2 v0 = unpack2(acc[2 * q]);
        float2 v1 = unpack2(acc[2 * q + 1]);
        float4 o = make_float4(v0.x + B[4 * q], v0.y + B[4 * q + 1],
                               v1.x + B[4 * q + 2], v1.y + B[4 * q + 3]);
        if (RESID) {
            float4 r = *(const float4*)(R + (size_t)p * OS + OC + 4 * q);
            o.x += r.x; o.y += r.y; o.z += r.z; o.w += r.w;
        }
        if (RELU) {
            o.x = fmaxf(o.x, 0.f); o.y = fmaxf(o.y, 0.f);
            o.z = fmaxf(o.z, 0.f); o.w = fmaxf(o.w, 0.f);
        }
        *(float4*)(op + 4 * q) = o;
    }
}

// ---------------------------------------------------------------------------
// Pointwise conv
// ---------------------------------------------------------------------------
template<int CIN, int COUT, bool RELU, bool RESID, int OSTRIDE, int OCOFF>
__global__ void pw_kernel(const float* __restrict__ X, const float* __restrict__ W,
                          const float* __restrict__ B, const float* __restrict__ R,
                          float* __restrict__ out, int Nout)
{
    __shared__ float Wsh[CIN * COUT];
    for (int e = threadIdx.x; e < CIN * COUT; e += blockDim.x) Wsh[e] = W[e];
    __syncthreads();

    int p = blockIdx.x * blockDim.x + threadIdx.x;
    if (p >= Nout) return;

    float acc[COUT];
#pragma unroll
    for (int c = 0; c < COUT; c++) acc[c] = B[c];

    const float4* xr = (const float4*)(X + (size_t)p * CIN);
#pragma unroll
    for (int c4 = 0; c4 < CIN / 4; c4++) {
        float4 v = xr[c4];
        const float* w0 = Wsh + (4 * c4) * COUT;
#pragma unroll
        for (int c = 0; c < COUT; c++) {
            acc[c] += v.x * w0[c] + v.y * w0[COUT + c]
                    + v.z * w0[2 * COUT + c] + v.w * w0[3 * COUT + c];
        }
    }
#pragma unroll
    for (int c = 0; c < COUT; c++) {
        float v = acc[c];
        if (RESID) v += R[(size_t)p * OSTRIDE + OCOFF + c];
        if (RELU)  v = fmaxf(v, 0.f);
        out[(size_t)p * OSTRIDE + OCOFF + c] = v;
    }
}

__global__ void add_kernel(const float* __restrict__ a, const float* __restrict__ b,
                           float* __restrict__ o, long long n4)
{
    long long i = blockIdx.x * (long long)blockDim.x + threadIdx.x;
    if (i < n4) {
        float4 x = ((const float4*)a)[i];
        float4 y = ((const float4*)b)[i];
        x.x += y.x; x.y += y.y; x.z += y.z; x.w += y.w;
        ((float4*)o)[i] = x;
    }
}

// ---------------------------------------------------------------------------
template<int K, int CIN, int COUT, int NTHR, int CG, int PTT,
         bool RELU, bool RESID, int OS, int OC, bool WSTREAM>
static void launch_tile(const float* X, const int* idxT, const float* W,
                        const float* B, const float* R, float* out, int Nout)
{
    constexpr int TP = (NTHR / CG) * PTT;
    constexpr int WS = WSTREAM ? 2 * CIN * COUT : K * CIN * COUT;
    constexpr int SMEM = (2 * TP * CIN + WS) * 4;
    auto kfn = spconv_tile<K, CIN, COUT, NTHR, CG, PTT, RELU, RESID, OS, OC, WSTREAM>;
    cudaFuncSetAttribute(kfn, cudaFuncAttributeMaxDynamicSharedMemorySize, SMEM);
    int grid = (Nout + TP - 1) / TP;
    kfn<<<grid, NTHR, SMEM>>>(X, idxT, W, B, R, out, Nout);
}

extern "C" void kernel_launch(void* const* d_in, const int* in_sizes, int n_in,
                              void* d_out, int out_size)
{
    const float* x_feat = (const float*)d_in[0];
    const float* f1_ref = (const float*)d_in[1];
    const float* w1   = (const float*)d_in[2];
    const float* b1   = (const float*)d_in[3];
    const float* wd   = (const float*)d_in[4];
    const float* bd   = (const float*)d_in[5];
    const float* rw00 = (const float*)d_in[6];
    const float* rb00 = (const float*)d_in[7];
    const float* rw01 = (const float*)d_in[8];
    const float* rb01 = (const float*)d_in[9];
    const float* rw10 = (const float*)d_in[10];
    const float* rb10 = (const float*)d_in[11];
    const float* rw11 = (const float*)d_in[12];
    const float* rb11 = (const float*)d_in[13];
    const float* rw12 = (const float*)d_in[14];
    const float* rb12 = (const float*)d_in[15];
    const float* w4   = (const float*)d_in[16];
    const float* b4   = (const float*)d_in[17];
    const int* idx1 = (const int*)d_in[18];
    const int* idxd = (const int*)d_in[19];
    const int* idx2 = (const int*)d_in[20];

    int N  = in_sizes[0] / 64;
    int N2 = in_sizes[19] / 8;

    float *X, *F1, *D0, *D1, *A8, *T8, *T8B;
    int *iT1, *iT2, *iTd;
    cudaGetSymbolAddress((void**)&X,   g_X);
    cudaGetSymbolAddress((void**)&F1,  g_F1);
    cudaGetSymbolAddress((void**)&D0,  g_D0);
    cudaGetSymbolAddress((void**)&D1,  g_D1);
    cudaGetSymbolAddress((void**)&A8,  g_A8);
    cudaGetSymbolAddress((void**)&T8,  g_T8);
    cudaGetSymbolAddress((void**)&T8B, g_T8B);
    cudaGetSymbolAddress((void**)&iT1, g_iT1);
    cudaGetSymbolAddress((void**)&iT2, g_iT2);
    cudaGetSymbolAddress((void**)&iTd, g_iTd);

    // index transposes (coalesced per-k loads in the conv kernels)
    transpose_idx<<<(N  + 255) / 256, 256>>>(idx1, iT1, N,  27);
    transpose_idx<<<(N2 + 255) / 256, 256>>>(idxd, iTd, N2, 8);
    transpose_idx<<<(N2 + 255) / 256, 256>>>(idx2, iT2, N2, 27);

    // x = x_feat + f1_ref
    long long n4 = (long long)N * 16;
    add_kernel<<<(int)((n4 + 255) / 256), 256>>>(x_feat, f1_ref, X, n4);

    // conv1: K=27, 64->64, relu (W streamed double-buffered)
    launch_tile<27, 64, 64, 128, 8, 8, true, false, 64, 0, true>(
        X, iT1, w1, b1, nullptr, F1, N);

    // down: K=8, 64->32, relu (W streamed)
    launch_tile<8, 64, 32, 128, 4, 4, true, false, 32, 0, true>(
        F1, iTd, wd, bd, nullptr, D0, N2);

    float* bufs[2] = { D0, D1 };
    for (int i = 0; i < 3; i++) {
        float* in = bufs[i & 1];
        float* ob = bufs[(i + 1) & 1];

        // a8 = relu(conv27(in, rw00))  32->8
        launch_tile<27, 32, 8, 256, 1, 1, true, false, 8, 0, false>(
            in, iT2, rw00 + (size_t)i * 27 * 32 * 8, rb00 + i * 8, nullptr, A8, N2);

        // out0 = conv27(a8, rw01) + in[:, :16]  8->16 -> ob[:, :16]
        spconv_direct8<27, 16, false, true, 32, 0><<<(N2 + 255) / 256, 256>>>(
            A8, iT2, rw01 + (size_t)i * 27 * 8 * 16, rb01 + i * 16, in, ob, N2);

        // t = relu(in @ rw10)  32->8
        pw_kernel<32, 8, true, false, 8, 0><<<(N2 + 255) / 256, 256>>>(
            in, rw10 + i * 32 * 8, rb10 + i * 8, nullptr, T8, N2);

        // t = relu(conv27(t, rw11))  8->8
        spconv_direct8<27, 8, true, false, 8, 0><<<(N2 + 255) / 256, 256>>>(
            T8, iT2, rw11 + (size_t)i * 27 * 8 * 8, rb11 + i * 8, nullptr, T8B, N2);

        // out1 = t @ rw12 + in[:, 16:]  -> ob[:, 16:]
        pw_kernel<8, 16, false, true, 32, 16><<<(N2 + 255) / 256, 256>>>(
            T8B, rw12 + i * 8 * 16, rb12 + i * 16, in, ob, N2);
    }

    // enc4: K=27, 32->8, no relu, straight to output
    launch_tile<27, 32, 8, 256, 1, 1, false, false, 8, 0, false>(
        bufs[1], iT2, w4, b4, nullptr, (float*)d_out, N2);
}

// round 4
// speedup vs baseline: 3.9877x; 1.9697x over previous
#include <cuda_runtime.h>
#include <cuda_bf16.h>

typedef unsigned long long u64;
typedef unsigned int u32;

#define MAXN 250048

// Scratch (allocation-free rule: __device__ globals)
__device__ float g_X  [(size_t)MAXN * 64];
__device__ float g_F1 [(size_t)MAXN * 64];
__device__ float g_D0 [(size_t)MAXN * 32];
__device__ float g_D1 [(size_t)MAXN * 32];
__device__ float g_A8 [(size_t)MAXN * 8];
__device__ float g_T8 [(size_t)MAXN * 8];
__device__ float g_T8B[(size_t)MAXN * 8];
__device__ int   g_iT1[(size_t)MAXN * 27];
__device__ int   g_iT2[(size_t)MAXN * 27];
__device__ int   g_iTd[(size_t)MAXN * 8];
// fragment-packed tf32 weights
__device__ float g_WF1[27 * 4096];   // conv1: K=27, Q=8, NT=8  -> 4096 floats/offset
__device__ float g_WFd[8 * 2048];    // down:  K=8,  Q=8, NT=4
__device__ float g_WF0[81 * 256];    // rw00 (3 blocks fused as K=81), Q=4, NT=1
__device__ float g_WF4[27 * 256];    // enc4

__device__ __forceinline__ u64 pack2(float x) {
    u64 r;
    asm("mov.b64 %0, {%1, %1};" : "=l"(r) : "r"(__float_as_uint(x)));
    return r;
}
__device__ __forceinline__ void fma2(u64& acc, u64 a, u64 b) {
    asm("fma.rn.f32x2 %0, %1, %2, %0;" : "+l"(acc) : "l"(a), "l"(b));
}
__device__ __forceinline__ float2 unpack2(u64 v) {
    float2 r;
    r.x = __uint_as_float((u32)(v & 0xffffffffull));
    r.y = __uint_as_float((u32)(v >> 32));
    return r;
}
__device__ __forceinline__ u32 smem_u32(const void* p) {
    return (u32)__cvta_generic_to_shared(p);
}
__device__ __forceinline__ void cpasync16(u32 dst, const void* src, u32 ssz) {
    asm volatile("cp.async.ca.shared.global [%0], [%1], 16, %2;\n"
                 :: "r"(dst), "l"(src), "r"(ssz));
}
__device__ __forceinline__ void cp_commit() {
    asm volatile("cp.async.commit_group;\n");
}
template<int N>
__device__ __forceinline__ void cp_wait() {
    asm volatile("cp.async.wait_group %0;\n" :: "n"(N));
}
__device__ __forceinline__ float rna_tf32(float x) {
    u32 y;
    asm("cvt.rna.tf32.f32 %0, %1;" : "=r"(y) : "f"(x));
    return __uint_as_float(y);
}
__device__ __forceinline__ void mma8(float4& d, const float* a, float2 b) {
    asm("mma.sync.aligned.m16n8k8.row.col.f32.tf32.tf32.f32 "
        "{%0,%1,%2,%3}, {%4,%5,%6,%7}, {%8,%9}, {%0,%1,%2,%3};"
        : "+f"(d.x), "+f"(d.y), "+f"(d.z), "+f"(d.w)
        : "r"(__float_as_uint(a[0])), "r"(__float_as_uint(a[1])),
          "r"(__float_as_uint(a[2])), "r"(__float_as_uint(a[3])),
          "r"(__float_as_uint(b.x)),  "r"(__float_as_uint(b.y)));
}

// ---------------------------------------------------------------------------
// idx transpose: outT[k*Npt + p] = in[p*K + k]
// ---------------------------------------------------------------------------
__global__ void transpose_idx(const int* __restrict__ in, int* __restrict__ outT,
                              int Npt, int K)
{
    int p = blockIdx.x * blockDim.x + threadIdx.x;
    if (p < Npt)
        for (int k = 0; k < K; k++)
            outT[(size_t)k * Npt + p] = in[(size_t)p * K + k];
}

// ---------------------------------------------------------------------------
// Weight prep: W[k][ci][co] fp32 -> tf32-rounded B-fragment order:
// Wf[(((k*Q + q)*NT + nt)*32 + lane)*2 + j] = W[k][q*8 + lane%4 + 4*j][nt*8 + lane/4]
// ---------------------------------------------------------------------------
__global__ void prep_wfrag(const float* __restrict__ W, float* __restrict__ Wf,
                           int K, int CIN, int COUT)
{
    int Q = CIN / 8, NT = COUT / 8;
    int total = K * Q * NT * 64;
    int e = blockIdx.x * 256 + threadIdx.x;
    if (e >= total) return;
    int j = e & 1;
    int lane = (e >> 1) & 31;
    int r = e >> 6;                 // ((k*Q + q)*NT + nt)
    int nt = r % NT; r /= NT;
    int q = r % Q;  int k = r / Q;
    int ci = q * 8 + (lane & 3) + 4 * j;
    int co = nt * 8 + (lane >> 2);
    Wf[e] = rna_tf32(W[((size_t)k * CIN + ci) * COUT + co]);
}

// ---------------------------------------------------------------------------
// tf32 mma.sync gather-GEMM sparse conv.
// 128 points/CTA, 4 warps; warp w handles rows [32w, 32w+32) as 2 m16 tiles.
// cp.async double-buffered over K offsets; accumulate across offsets in regs.
// A gathered with 16B XOR swizzle; W pre-packed in fragment order.
// ---------------------------------------------------------------------------
template<int K, int CIN, int COUT, bool RELU, bool CVTOUT>
__global__ void __launch_bounds__(128)
tf32_conv(const float* __restrict__ X, const int* __restrict__ idxT,
          const float* __restrict__ Wf, const float* __restrict__ Bb,
          float* __restrict__ out, int Nout)
{
    constexpr int Q    = CIN / 8;
    constexpr int NT   = COUT / 8;
    constexpr int ASTG = 128 * CIN;       // floats per A stage
    constexpr int WSTG = Q * NT * 64;     // floats per W stage
    constexpr int C4U  = CIN / 4;

    extern __shared__ float sm[];
    float* A0 = sm;
    float* A1 = sm + ASTG;
    float* W0 = sm + 2 * ASTG;
    float* W1 = W0 + WSTG;

    const int tid = threadIdx.x, wid = tid >> 5, lane = tid & 31;
    const int r7 = lane >> 2;             // row-in-8 & swizzle key
    const int cl = lane & 3;
    const int p0 = blockIdx.x * 128;
    const int gp = p0 + tid;
    const bool pv = gp < Nout;

    const u32 ab0 = smem_u32(A0), ab1 = smem_u32(A1);
    const u32 wb0 = smem_u32(W0), wb1 = smem_u32(W1);

    auto prefetch = [&](int k, int b) {
        int src = pv ? idxT[(size_t)k * Nout + gp] : -1;
        const float* srow = X + (size_t)(src >= 0 ? src : 0) * CIN;
        u32 ssz = (src >= 0) ? 16u : 0u;
        u32 base = (b ? ab1 : ab0) + (u32)tid * (CIN * 4);
#pragma unroll
        for (int c4 = 0; c4 < C4U; c4++)
            cpasync16(base + ((u32)(c4 ^ (tid & 7)) << 4), srow + 4 * c4, ssz);
        const float4* wg = (const float4*)(Wf + (size_t)k * WSTG);
        u32 wdst = b ? wb1 : wb0;
        for (int e = tid; e < WSTG / 4; e += 128)
            cpasync16(wdst + 16u * e, wg + e, 16);
    };

    prefetch(0, 0);
    cp_commit();

    float4 acc[2][NT];
#pragma unroll
    for (int m = 0; m < 2; m++)
#pragma unroll
        for (int nt = 0; nt < NT; nt++)
            acc[m][nt] = make_float4(0.f, 0.f, 0.f, 0.f);

#pragma unroll 1
    for (int k = 0; k < K; k++) {
        __syncthreads();
        if (k + 1 < K) { prefetch(k + 1, (k + 1) & 1); cp_commit(); cp_wait<1>(); }
        else           { cp_wait<0>(); }
        __syncthreads();

        const float* A  = (k & 1) ? A1 : A0;
        const float* Wk = (k & 1) ? W1 : W0;

#pragma unroll
        for (int q = 0; q < Q; q++) {
            const int c4a = ((2 * q) ^ r7) << 2;
            const int c4b = ((2 * q + 1) ^ r7) << 2;
            float a[2][4];
#pragma unroll
            for (int m = 0; m < 2; m++) {
                const int rl = wid * 32 + m * 16 + r7;
                a[m][0] = A[rl * CIN + c4a + cl];
                a[m][1] = A[(rl + 8) * CIN + c4a + cl];
                a[m][2] = A[rl * CIN + c4b + cl];
                a[m][3] = A[(rl + 8) * CIN + c4b + cl];
            }
#pragma unroll
            for (int nt = 0; nt < NT; nt++) {
                float2 b = *(const float2*)(Wk + ((q * NT + nt) * 32 + lane) * 2);
                mma8(acc[0][nt], a[0], b);
                mma8(acc[1][nt], a[1], b);
            }
        }
    }

    // epilogue: bias (+relu) (+tf32-round), direct global stores
#pragma unroll
    for (int m = 0; m < 2; m++) {
        const int rlo = p0 + wid * 32 + m * 16 + r7;
        const int rhi = rlo + 8;
#pragma unroll
        for (int nt = 0; nt < NT; nt++) {
            const int c0 = nt * 8 + 2 * cl;
            const float b0 = Bb[c0], b1 = Bb[c0 + 1];
            float2 v0 = make_float2(acc[m][nt].x + b0, acc[m][nt].y + b1);
            float2 v1 = make_float2(acc[m][nt].z + b0, acc[m][nt].w + b1);
            if (RELU) {
                v0.x = fmaxf(v0.x, 0.f); v0.y = fmaxf(v0.y, 0.f);
                v1.x = fmaxf(v1.x, 0.f); v1.y = fmaxf(v1.y, 0.f);
            }
            if (CVTOUT) {
                v0.x = rna_tf32(v0.x); v0.y = rna_tf32(v0.y);
                v1.x = rna_tf32(v1.x); v1.y = rna_tf32(v1.y);
            }
            if (rlo < Nout) *(float2*)(out + (size_t)rlo * COUT + c0) = v0;
            if (rhi < Nout) *(float2*)(out + (size_t)rhi * COUT + c0) = v1;
        }
    }
}

// ---------------------------------------------------------------------------
// Direct sparse conv for CIN=8 (rows are 32B), fp32 f32x2 path
// ---------------------------------------------------------------------------
template<int K, int COUT, bool RELU, bool RESID, int OS, int OC>
__global__ void __launch_bounds__(256)
spconv_direct8(const float* __restrict__ X, const int* __restrict__ idxT,
               const float* __restrict__ W, const float* __restrict__ B,
               const float* __restrict__ R, float* __restrict__ out, int Nout)
{
    constexpr int NA = COUT / 2;
    __shared__ float Wsh[K * 8 * COUT];
    for (int e = threadIdx.x; e < K * 8 * COUT; e += 256) Wsh[e] = W[e];
    __syncthreads();

    const int p = blockIdx.x * 256 + threadIdx.x;
    if (p >= Nout) return;

    u64 acc[NA];
#pragma unroll
    for (int c = 0; c < NA; c++) acc[c] = 0ull;

    const float4 z4 = make_float4(0.f, 0.f, 0.f, 0.f);
    int s_nxt = (K > 1) ? idxT[(size_t)Nout + p] : -1;
    int s0 = idxT[p];
    float4 a0 = z4, a1 = z4;
    if (s0 >= 0) {
        const float4* r = (const float4*)(X + (size_t)s0 * 8);
        a0 = r[0]; a1 = r[1];
    }

#pragma unroll 1
    for (int k = 0; k < K; k++) {
        float4 b0 = z4, b1 = z4;
        if (k + 1 < K) {
            if (s_nxt >= 0) {
                const float4* r = (const float4*)(X + (size_t)s_nxt * 8);
                b0 = r[0]; b1 = r[1];
            }
            s_nxt = (k + 2 < K) ? idxT[(size_t)(k + 2) * Nout + p] : -1;
        }
        const float* wk = Wsh + k * 8 * COUT;
        const float g[8] = { a0.x, a0.y, a0.z, a0.w, a1.x, a1.y, a1.z, a1.w };
#pragma unroll
        for (int ci = 0; ci < 8; ci++) {
            u64 g2 = pack2(g[ci]);
            const u64* wr = (const u64*)(wk + ci * COUT);
#pragma unroll
            for (int cc = 0; cc < NA; cc++)
                fma2(acc[cc], g2, wr[cc]);
        }
        a0 = b0; a1 = b1;
    }

    float* op = out + (size_t)p * OS + OC;
#pragma unroll
    for (int q = 0; q < NA / 2; q++) {
        float2 v0 = unpack2(acc[2 * q]);
        float2 v1 = unpack2(acc[2 * q + 1]);
        float4 o = make_float4(v0.x + B[4 * q], v0.y + B[4 * q + 1],
                               v1.x + B[4 * q + 2], v1.y + B[4 * q + 3]);
        if (RESID) {
            float4 r = *(const float4*)(R + (size_t)p * OS + OC + 4 * q);
            o.x += r.x; o.y += r.y; o.z += r.z; o.w += r.w;
        }
        if (RELU) {
            o.x = fmaxf(o.x, 0.f); o.y = fmaxf(o.y, 0.f);
            o.z = fmaxf(o.z, 0.f); o.w = fmaxf(o.w, 0.f);
        }
        *(float4*)(op + 4 * q) = o;
    }
}

// ---------------------------------------------------------------------------
// Pointwise conv
// ---------------------------------------------------------------------------
template<int CIN, int COUT, bool RELU, bool RESID, int OSTRIDE, int OCOFF>
__global__ void pw_kernel(const float* __restrict__ X, const float* __restrict__ W,
                          const float* __restrict__ B, const float* __restrict__ R,
                          float* __restrict__ out, int Nout)
{
    __shared__ float Wsh[CIN * COUT];
    for (int e = threadIdx.x; e < CIN * COUT; e += blockDim.x) Wsh[e] = W[e];
    __syncthreads();

    int p = blockIdx.x * blockDim.x + threadIdx.x;
    if (p >= Nout) return;

    float acc[COUT];
#pragma unroll
    for (int c = 0; c < COUT; c++) acc[c] = B[c];

    const float4* xr = (const float4*)(X + (size_t)p * CIN);
#pragma unroll
    for (int c4 = 0; c4 < CIN / 4; c4++) {
        float4 v = xr[c4];
        const float* w0 = Wsh + (4 * c4) * COUT;
#pragma unroll
        for (int c = 0; c < COUT; c++) {
            acc[c] += v.x * w0[c] + v.y * w0[COUT + c]
                    + v.z * w0[2 * COUT + c] + v.w * w0[3 * COUT + c];
        }
    }
#pragma unroll
    for (int c = 0; c < COUT; c++) {
        float v = acc[c];
        if (RESID) v += R[(size_t)p * OSTRIDE + OCOFF + c];
        if (RELU)  v = fmaxf(v, 0.f);
        out[(size_t)p * OSTRIDE + OCOFF + c] = v;
    }
}

template<bool CVT>
__global__ void add_kernel(const float* __restrict__ a, const float* __restrict__ b,
                           float* __restrict__ o, long long n4)
{
    long long i = blockIdx.x * (long long)blockDim.x + threadIdx.x;
    if (i < n4) {
        float4 x = ((const float4*)a)[i];
        float4 y = ((const float4*)b)[i];
        x.x += y.x; x.y += y.y; x.z += y.z; x.w += y.w;
        if (CVT) {
            x.x = rna_tf32(x.x); x.y = rna_tf32(x.y);
            x.z = rna_tf32(x.z); x.w = rna_tf32(x.w);
        }
        ((float4*)o)[i] = x;
    }
}

// ---------------------------------------------------------------------------
template<int K, int CIN, int COUT, bool RELU, bool CVTOUT>
static void launch_tf32(const float* X, const int* idxT, const float* Wf,
                        const float* B, float* out, int Nout)
{
    constexpr int SMEM = (2 * 128 * CIN + 2 * (CIN / 8) * (COUT / 8) * 64) * 4;
    auto kfn = tf32_conv<K, CIN, COUT, RELU, CVTOUT>;
    cudaFuncSetAttribute(kfn, cudaFuncAttributeMaxDynamicSharedMemorySize, SMEM);
    int grid = (Nout + 127) / 128;
    kfn<<<grid, 128, SMEM>>>(X, idxT, Wf, B, out, Nout);
}

extern "C" void kernel_launch(void* const* d_in, const int* in_sizes, int n_in,
                              void* d_out, int out_size)
{
    const float* x_feat = (const float*)d_in[0];
    const float* f1_ref = (const float*)d_in[1];
    const float* w1   = (const float*)d_in[2];
    const float* b1   = (const float*)d_in[3];
    const float* wd   = (const float*)d_in[4];
    const float* bd   = (const float*)d_in[5];
    const float* rw00 = (const float*)d_in[6];
    const float* rb00 = (const float*)d_in[7];
    const float* rw01 = (const float*)d_in[8];
    const float* rb01 = (const float*)d_in[9];
    const float* rw10 = (const float*)d_in[10];
    const float* rb10 = (const float*)d_in[11];
    const float* rw11 = (const float*)d_in[12];
    const float* rb11 = (const float*)d_in[13];
    const float* rw12 = (const float*)d_in[14];
    const float* rb12 = (const float*)d_in[15];
    const float* w4   = (const float*)d_in[16];
    const float* b4   = (const float*)d_in[17];
    const int* idx1 = (const int*)d_in[18];
    const int* idxd = (const int*)d_in[19];
    const int* idx2 = (const int*)d_in[20];

    int N  = in_sizes[0] / 64;
    int N2 = in_sizes[19] / 8;

    float *X, *F1, *D0, *D1, *A8, *T8, *T8B;
    float *WF1, *WFd, *WF0, *WF4;
    int *iT1, *iT2, *iTd;
    cudaGetSymbolAddress((void**)&X,   g_X);
    cudaGetSymbolAddress((void**)&F1,  g_F1);
    cudaGetSymbolAddress((void**)&D0,  g_D0);
    cudaGetSymbolAddress((void**)&D1,  g_D1);
    cudaGetSymbolAddress((void**)&A8,  g_A8);
    cudaGetSymbolAddress((void**)&T8,  g_T8);
    cudaGetSymbolAddress((void**)&T8B, g_T8B);
    cudaGetSymbolAddress((void**)&iT1, g_iT1);
    cudaGetSymbolAddress((void**)&iT2, g_iT2);
    cudaGetSymbolAddress((void**)&iTd, g_iTd);
    cudaGetSymbolAddress((void**)&WF1, g_WF1);
    cudaGetSymbolAddress((void**)&WFd, g_WFd);
    cudaGetSymbolAddress((void**)&WF0, g_WF0);
    cudaGetSymbolAddress((void**)&WF4, g_WF4);

    // prep: transposed idx + fragment-packed tf32 weights
    transpose_idx<<<(N  + 255) / 256, 256>>>(idx1, iT1, N,  27);
    transpose_idx<<<(N2 + 255) / 256, 256>>>(idxd, iTd, N2, 8);
    transpose_idx<<<(N2 + 255) / 256, 256>>>(idx2, iT2, N2, 27);
    prep_wfrag<<<(27 * 4096 + 255) / 256, 256>>>(w1,   WF1, 27, 64, 64);
    prep_wfrag<<<(8 * 2048 + 255) / 256, 256>>>(wd,    WFd, 8,  64, 32);
    prep_wfrag<<<(81 * 256 + 255) / 256, 256>>>(rw00,  WF0, 81, 32, 8);
    prep_wfrag<<<(27 * 256 + 255) / 256, 256>>>(w4,    WF4, 27, 32, 8);

    // x = tf32(x_feat + f1_ref)
    long long n4 = (long long)N * 16;
    add_kernel<true><<<(int)((n4 + 255) / 256), 256>>>(x_feat, f1_ref, X, n4);

    // conv1: K=27, 64->64, relu (epilogue rounds to tf32 for `down`)
    launch_tf32<27, 64, 64, true, true>(X, iT1, WF1, b1, F1, N);

    // down: K=8, 64->32, relu
    launch_tf32<8, 64, 32, true, false>(F1, iTd, WFd, bd, D0, N2);

    float* bufs[2] = { D0, D1 };
    for (int i = 0; i < 3; i++) {
        float* in = bufs[i & 1];
        float* ob = bufs[(i + 1) & 1];

        // a8 = relu(conv27(in, rw00))  32->8
        launch_tf32<27, 32, 8, true, false>(
            in, iT2, WF0 + (size_t)i * 27 * 256, rb00 + i * 8, A8, N2);

        // out0 = conv27(a8, rw01) + in[:, :16]  8->16 -> ob[:, :16]
        spconv_direct8<27, 16, false, true, 32, 0><<<(N2 + 255) / 256, 256>>>(
            A8, iT2, rw01 + (size_t)i * 27 * 8 * 16, rb01 + i * 16, in, ob, N2);

        // t = relu(in @ rw10)  32->8
        pw_kernel<32, 8, true, false, 8, 0><<<(N2 + 255) / 256, 256>>>(
            in, rw10 + i * 32 * 8, rb10 + i * 8, nullptr, T8, N2);

        // t = relu(conv27(t, rw11))  8->8
        spconv_direct8<27, 8, true, false, 8, 0><<<(N2 + 255) / 256, 256>>>(
            T8, iT2, rw11 + (size_t)i * 27 * 8 * 8, rb11 + i * 8, nullptr, T8B, N2);

        // out1 = t @ rw12 + in[:, 16:]  -> ob[:, 16:]
        pw_kernel<8, 16, false, true, 32, 16><<<(N2 + 255) / 256, 256>>>(
            T8B, rw12 + i * 8 * 16, rb12 + i * 16, in, ob, N2);
    }

    // enc4: K=27, 32->8, no relu, straight to output
    launch_tf32<27, 32, 8, false, false>(bufs[1], iT2, WF4, b4, (float*)d_out, N2);
}